// round 3
// baseline (speedup 1.0000x reference)
#include <cuda_runtime.h>

#define N_SLOTS 524288
#define DIM     128
#define NF      138        // DIM_MEM + 1 + 1 + 7 + 1
#define DIN     1024
#define TILE    128
#define HALO    3
#define TPB     256
#define NWARPS  8
#define NTILES  (N_SLOTS / TILE)    // 4096
#define MAIN_BLOCKS 456             // 3 per SM on 152 SMs

// scratch (allocation-free: __device__ globals)
__device__ __align__(16) float g_factors[144];
__device__ float g_shift[7];
__device__ float g_key_s, g_stab, g_inv_keynorm, g_sharp;
__device__ float g_Upart[MAIN_BLOCKS][DIM];
__device__ float g_Zpart[MAIN_BLOCKS];

// ---------------- K1: factors = x @ W + b (one block per factor) ----------------
__global__ void k_factors(const float* __restrict__ x,
                          const float* __restrict__ W,
                          const float* __restrict__ b) {
    const int f = blockIdx.x;
    const int tid = threadIdx.x;
    float acc = 0.f;
    #pragma unroll 4
    for (int k = tid; k < DIN; k += 256)
        acc += x[k] * __ldg(&W[k * NF + f]);
    __shared__ float red[256];
    red[tid] = acc;
    __syncthreads();
    for (int s = 128; s > 0; s >>= 1) {
        if (tid < s) red[tid] += red[tid + s];
        __syncthreads();
    }
    if (tid == 0) g_factors[f] = red[0] + b[f];
}

// ---------------- K2: derived scalars ----------------
__global__ void k_prep() {
    const int tid = threadIdx.x;   // 128 threads
    float kv = (tid < DIM) ? g_factors[tid] : 0.f;
    float sq = kv * kv;
    __shared__ float warpsum[4];
    #pragma unroll
    for (int o = 16; o; o >>= 1) sq += __shfl_xor_sync(0xffffffffu, sq, o);
    if ((tid & 31) == 0) warpsum[tid >> 5] = sq;
    __syncthreads();
    if (tid == 0) {
        float total = warpsum[0] + warpsum[1] + warpsum[2] + warpsum[3];
        g_inv_keynorm = 1.f / fmaxf(sqrtf(total), 1e-8f);
        const float ks = g_factors[DIM];       // key strength
        g_key_s = ks;
        g_stab  = fabsf(ks);                   // bound of |ks * cosine|
        // shift softmax over factors[130..136]
        float mx = -1e30f;
        #pragma unroll
        for (int j = 0; j < 7; j++) mx = fmaxf(mx, g_factors[DIM + 2 + j]);
        float ssum = 0.f, ev[7];
        #pragma unroll
        for (int j = 0; j < 7; j++) { ev[j] = expf(g_factors[DIM + 2 + j] - mx); ssum += ev[j]; }
        #pragma unroll
        for (int j = 0; j < 7; j++) g_shift[j] = ev[j] / ssum;
        g_sharp = fmaxf(g_factors[NF - 1], 0.f) + 1.f;
    }
    // NOTE: gate = softmax(single element) == 1.0 exactly -> previous_weighting unused.
}

// ---------------- K3: fused single pass over memory ----------------
// smem: tile[TILE*DIM] | e[136] ; tile reused as reduction scratch at the end
__global__ void __launch_bounds__(TPB, 3) k_main(const float* __restrict__ mem) {
    extern __shared__ float smem[];
    float* sTile = smem;
    float* sE    = sTile + TILE * DIM;

    const int tid  = threadIdx.x;
    const int warp = tid >> 5;
    const int lane = tid & 31;

    const float4 kv = ((const float4*)g_factors)[lane];   // key cols [4*lane, 4*lane+4)
    const float ks = g_key_s, stab = g_stab, ikn = g_inv_keynorm, sharp = g_sharp;
    float sh[7];
    #pragma unroll
    for (int j = 0; j < 7; j++) sh[j] = g_shift[j];

    float4 acc = make_float4(0.f, 0.f, 0.f, 0.f);
    float zacc = 0.f;

    for (int t = blockIdx.x; t < NTILES; t += gridDim.x) {
        const int gStart = t * TILE;
        __syncthreads();   // smem reuse barrier

        // Phase A: rows local l in [0, TILE+6); global row = (gStart+l-3) mod N.
        // Dual-row processing for 2 outstanding 512B loads per warp.
        for (int l0 = warp; l0 < TILE + 2 * HALO; l0 += 2 * NWARPS) {
            const int  l1   = l0 + NWARPS;
            const bool has1 = (l1 < TILE + 2 * HALO);
            int g0 = gStart + l0 - HALO;
            g0 += (g0 < 0) ? N_SLOTS : 0;
            g0 -= (g0 >= N_SLOTS) ? N_SLOTS : 0;
            const float4 m0 = ((const float4*)(mem + (size_t)g0 * DIM))[lane];
            float4 m1 = make_float4(0.f, 0.f, 0.f, 0.f);
            if (has1) {
                int g1 = gStart + l1 - HALO;
                g1 += (g1 < 0) ? N_SLOTS : 0;
                g1 -= (g1 >= N_SLOTS) ? N_SLOTS : 0;
                m1 = ((const float4*)(mem + (size_t)g1 * DIM))[lane];
            }
            if ((unsigned)(l0 - HALO) < TILE)
                ((float4*)(sTile + (l0 - HALO) * DIM))[lane] = m0;
            if (has1 && (unsigned)(l1 - HALO) < TILE)
                ((float4*)(sTile + (l1 - HALO) * DIM))[lane] = m1;

            float d0 = m0.x*kv.x + m0.y*kv.y + m0.z*kv.z + m0.w*kv.w;
            float q0 = m0.x*m0.x + m0.y*m0.y + m0.z*m0.z + m0.w*m0.w;
            float d1 = m1.x*kv.x + m1.y*kv.y + m1.z*kv.z + m1.w*kv.w;
            float q1 = m1.x*m1.x + m1.y*m1.y + m1.z*m1.z + m1.w*m1.w;
            #pragma unroll
            for (int o = 16; o; o >>= 1) {
                d0 += __shfl_xor_sync(0xffffffffu, d0, o);
                q0 += __shfl_xor_sync(0xffffffffu, q0, o);
                d1 += __shfl_xor_sync(0xffffffffu, d1, o);
                q1 += __shfl_xor_sync(0xffffffffu, q1, o);
            }
            if (lane == 0) {
                // cosine sim; e = exp(ks*c - |ks|)  (constant factor cancels in final normalization)
                const float c0 = d0 * ikn / fmaxf(sqrtf(q0), 1e-8f);
                sE[l0] = __expf(ks * c0 - stab);
                if (has1) {
                    const float c1 = d1 * ikn / fmaxf(sqrtf(q1), 1e-8f);
                    sE[l1] = __expf(ks * c1 - stab);
                }
            }
        }
        __syncthreads();

        // Phase B: warp handles 16 rows; lanes 0..15 compute pw for one row each.
        const int base = warp * (TILE / NWARPS);
        float pw = 0.f;
        if (lane < (TILE / NWARPS)) {
            float tc = 0.f;
            #pragma unroll
            for (int j = 0; j < 7; j++) tc += sh[j] * sE[base + lane + j];
            pw = powf(tc, sharp);    // > 0 always (e>0, softmax shift weights>0)
            zacc += pw;
        }
        #pragma unroll 4
        for (int r = 0; r < (TILE / NWARPS); r++) {
            const float pwb = __shfl_sync(0xffffffffu, pw, r);
            const float4 m = ((const float4*)(sTile + (base + r) * DIM))[lane];
            acc.x += pwb * m.x; acc.y += pwb * m.y;
            acc.z += pwb * m.z; acc.w += pwb * m.w;
        }
    }

    // Deterministic in-block reduction: per-warp partials into sTile scratch.
    __syncthreads();
    ((float4*)(sTile + warp * DIM))[lane] = acc;   // sTile[warp][dim]
    #pragma unroll
    for (int o = 16; o; o >>= 1) zacc += __shfl_xor_sync(0xffffffffu, zacc, o);
    if (lane == 0) sE[warp] = zacc;
    __syncthreads();
    if (tid < DIM) {
        float u = 0.f;
        #pragma unroll
        for (int w = 0; w < NWARPS; w++) u += sTile[w * DIM + tid];
        g_Upart[blockIdx.x][tid] = u;
    }
    if (tid == 0) {
        float z = 0.f;
        #pragma unroll
        for (int w = 0; w < NWARPS; w++) z += sE[w];
        g_Zpart[blockIdx.x] = z;
    }
}

// ---------------- K4: final deterministic reduction + normalize ----------------
__global__ void k_fin(float* __restrict__ out) {
    const int t = threadIdx.x;   // 128 threads
    __shared__ float sz[128];
    float z = 0.f;
    for (int i = t; i < MAIN_BLOCKS; i += 128) z += g_Zpart[i];
    sz[t] = z;
    __syncthreads();
    for (int s = 64; s > 0; s >>= 1) {
        if (t < s) sz[t] += sz[t + s];
        __syncthreads();
    }
    float u = 0.f;
    #pragma unroll 8
    for (int i = 0; i < MAIN_BLOCKS; i++) u += g_Upart[i][t];
    out[t] = u / sz[0];
}

static const int SMEM_BYTES = (TILE * DIM + 136) * (int)sizeof(float);

extern "C" void kernel_launch(void* const* d_in, const int* in_sizes, int n_in,
                              void* d_out, int out_size) {
    // Bind inputs by UNIQUE element count (robust to metadata ordering):
    // x=1024, prev=524288 (unused: gate==1), mem=67108864, W=141312, b=138
    const float *x = 0, *mem = 0, *W = 0, *b = 0;
    for (int i = 0; i < n_in; i++) {
        switch (in_sizes[i]) {
            case DIN:            x   = (const float*)d_in[i]; break;
            case N_SLOTS * DIM:  mem = (const float*)d_in[i]; break;
            case DIN * NF:       W   = (const float*)d_in[i]; break;
            case NF:             b   = (const float*)d_in[i]; break;
            default: break;      // previous_weighting (N_SLOTS): unused
        }
    }
    float* out = (float*)d_out;

    cudaFuncSetAttribute(k_main, cudaFuncAttributeMaxDynamicSharedMemorySize, SMEM_BYTES);

    k_factors<<<NF, 256>>>(x, W, b);
    k_prep<<<1, 128>>>();
    k_main<<<MAIN_BLOCKS, TPB, SMEM_BYTES>>>(mem);
    k_fin<<<1, 128>>>(out);
}

// round 4
// speedup vs baseline: 1.0337x; 1.0337x over previous
#include <cuda_runtime.h>

#define N_SLOTS 524288
#define DIM     128
#define NF      138        // DIM_MEM + 1 + 1 + 7 + 1
#define DIN     1024
#define TILE    128
#define HALO    3
#define TPB     256
#define NWARPS  8
#define NTILES  (N_SLOTS / TILE)    // 4096
#define MAIN_BLOCKS 456             // 3 per SM on 152 SMs

// scratch (allocation-free: __device__ globals)
__device__ __align__(16) float g_factors[144];
__device__ float g_shift[7];
__device__ float g_key_s, g_stab, g_inv_keynorm, g_sharp;
__device__ __align__(16) float g_Upart[MAIN_BLOCKS][DIM];
__device__ float g_Zpart[MAIN_BLOCKS];

// ---------------- K1: factors = x @ W + b ----------------
// Block b owns factors [32b, 32b+32); lane = factor offset -> coalesced W reads.
__global__ void k_factors(const float* __restrict__ x,
                          const float* __restrict__ W,
                          const float* __restrict__ b) {
    __shared__ float su[NWARPS][32];
    const int tid  = threadIdx.x;
    const int warp = tid >> 5;
    const int lane = tid & 31;
    const int f    = blockIdx.x * 32 + lane;
    float acc = 0.f;
    if (f < NF) {
        #pragma unroll 4
        for (int k = warp; k < DIN; k += NWARPS)
            acc += __ldg(&x[k]) * __ldg(&W[k * NF + f]);
    }
    su[warp][lane] = acc;
    __syncthreads();
    if (tid < 32 && f < NF) {
        float s = 0.f;
        #pragma unroll
        for (int w = 0; w < NWARPS; w++) s += su[w][lane];
        g_factors[f] = s + b[f];
    }
}

// ---------------- K2: derived scalars ----------------
__global__ void k_prep() {
    const int tid = threadIdx.x;   // 128 threads
    float kv = (tid < DIM) ? g_factors[tid] : 0.f;
    float sq = kv * kv;
    __shared__ float warpsum[4];
    #pragma unroll
    for (int o = 16; o; o >>= 1) sq += __shfl_xor_sync(0xffffffffu, sq, o);
    if ((tid & 31) == 0) warpsum[tid >> 5] = sq;
    __syncthreads();
    if (tid == 0) {
        float total = warpsum[0] + warpsum[1] + warpsum[2] + warpsum[3];
        g_inv_keynorm = 1.f / fmaxf(sqrtf(total), 1e-8f);
        const float ks = g_factors[DIM];       // key strength
        g_key_s = ks;
        g_stab  = fabsf(ks);                   // bound of |ks * cosine|
        float mx = -1e30f;
        #pragma unroll
        for (int j = 0; j < 7; j++) mx = fmaxf(mx, g_factors[DIM + 2 + j]);
        float ssum = 0.f, ev[7];
        #pragma unroll
        for (int j = 0; j < 7; j++) { ev[j] = expf(g_factors[DIM + 2 + j] - mx); ssum += ev[j]; }
        #pragma unroll
        for (int j = 0; j < 7; j++) g_shift[j] = ev[j] / ssum;
        g_sharp = fmaxf(g_factors[NF - 1], 0.f) + 1.f;
    }
    // gate = softmax(single element) == 1.0 exactly -> previous_weighting unused.
}

// ---------------- K3: fused single pass over memory ----------------
// smem: tile[TILE*DIM] | e[136] ; tile reused as reduction scratch at the end
__global__ void __launch_bounds__(TPB, 3) k_main(const float* __restrict__ mem) {
    extern __shared__ float smem[];
    float* sTile = smem;
    float* sE    = sTile + TILE * DIM;

    const int tid  = threadIdx.x;
    const int warp = tid >> 5;
    const int lane = tid & 31;

    const float4 kv = ((const float4*)g_factors)[lane];   // key cols [4*lane, 4*lane+4)
    const float ks = g_key_s, stab = g_stab, ikn = g_inv_keynorm, sharp = g_sharp;
    float sh[7];
    #pragma unroll
    for (int j = 0; j < 7; j++) sh[j] = g_shift[j];

    float4 acc = make_float4(0.f, 0.f, 0.f, 0.f);
    float zacc = 0.f;

    for (int t = blockIdx.x; t < NTILES; t += gridDim.x) {
        const int gStart = t * TILE;
        __syncthreads();   // smem reuse barrier

        // Phase A: rows l in [0, 134); global row = (gStart+l-3) mod N.
        // 4 rows per warp per iteration -> 4 outstanding 512B loads per warp.
        for (int l0 = warp; l0 < TILE + 2 * HALO; l0 += 4 * NWARPS) {
            int   l[4]; bool has[4]; float4 m[4];
            #pragma unroll
            for (int u = 0; u < 4; u++) {
                l[u]   = l0 + u * NWARPS;
                has[u] = (l[u] < TILE + 2 * HALO);
                m[u]   = make_float4(0.f, 0.f, 0.f, 0.f);
                if (has[u]) {
                    int g = gStart + l[u] - HALO;
                    g += (g < 0) ? N_SLOTS : 0;
                    g -= (g >= N_SLOTS) ? N_SLOTS : 0;
                    m[u] = ((const float4*)(mem + (size_t)g * DIM))[lane];
                }
            }
            #pragma unroll
            for (int u = 0; u < 4; u++)
                if (has[u] && (unsigned)(l[u] - HALO) < TILE)
                    ((float4*)(sTile + (l[u] - HALO) * DIM))[lane] = m[u];

            float d[4], q[4];
            #pragma unroll
            for (int u = 0; u < 4; u++) {
                d[u] = m[u].x*kv.x + m[u].y*kv.y + m[u].z*kv.z + m[u].w*kv.w;
                q[u] = m[u].x*m[u].x + m[u].y*m[u].y + m[u].z*m[u].z + m[u].w*m[u].w;
            }
            #pragma unroll
            for (int o = 16; o; o >>= 1) {
                #pragma unroll
                for (int u = 0; u < 4; u++) {
                    d[u] += __shfl_xor_sync(0xffffffffu, d[u], o);
                    q[u] += __shfl_xor_sync(0xffffffffu, q[u], o);
                }
            }
            if (lane == 0) {
                #pragma unroll
                for (int u = 0; u < 4; u++) {
                    if (has[u]) {
                        // e = exp(ks*cos - |ks|); constant factor cancels in final normalization
                        const float c = d[u] * ikn / fmaxf(sqrtf(q[u]), 1e-8f);
                        sE[l[u]] = __expf(ks * c - stab);
                    }
                }
            }
        }
        __syncthreads();

        // Phase B: warp handles 16 rows; lanes 0..15 compute pw for one row each.
        const int base = warp * (TILE / NWARPS);
        float pw = 0.f;
        if (lane < (TILE / NWARPS)) {
            float tc = 0.f;
            #pragma unroll
            for (int j = 0; j < 7; j++) tc += sh[j] * sE[base + lane + j];
            pw = powf(tc, sharp);    // > 0 always (e>0, shift weights>0)
            zacc += pw;
        }
        #pragma unroll 4
        for (int r = 0; r < (TILE / NWARPS); r++) {
            const float pwb = __shfl_sync(0xffffffffu, pw, r);
            const float4 m = ((const float4*)(sTile + (base + r) * DIM))[lane];
            acc.x += pwb * m.x; acc.y += pwb * m.y;
            acc.z += pwb * m.z; acc.w += pwb * m.w;
        }
    }

    // Deterministic in-block reduction: per-warp partials into sTile scratch.
    __syncthreads();
    ((float4*)(sTile + warp * DIM))[lane] = acc;   // sTile[warp][dim]
    #pragma unroll
    for (int o = 16; o; o >>= 1) zacc += __shfl_xor_sync(0xffffffffu, zacc, o);
    if (lane == 0) sE[warp] = zacc;
    __syncthreads();
    if (tid < DIM) {
        float u = 0.f;
        #pragma unroll
        for (int w = 0; w < NWARPS; w++) u += sTile[w * DIM + tid];
        g_Upart[blockIdx.x][tid] = u;
    }
    if (tid == 0) {
        float z = 0.f;
        #pragma unroll
        for (int w = 0; w < NWARPS; w++) z += sE[w];
        g_Zpart[blockIdx.x] = z;
    }
}

// ---------------- K4: final deterministic reduction + normalize ----------------
// 1024 threads: 32 row-groups x 32 lanes, float4 loads (coalesced 512B/warp).
__global__ void k_fin(float* __restrict__ out) {
    __shared__ float su[32][DIM];     // 16 KB
    __shared__ float sz[32];
    const int tid  = threadIdx.x;
    const int lane = tid & 31;
    const int row  = tid >> 5;        // 0..31

    float4 u = make_float4(0.f, 0.f, 0.f, 0.f);
    for (int i = row; i < MAIN_BLOCKS; i += 32) {
        const float4 v = ((const float4*)g_Upart[i])[lane];
        u.x += v.x; u.y += v.y; u.z += v.z; u.w += v.w;
    }
    ((float4*)su[row])[lane] = u;

    float z = (tid < MAIN_BLOCKS) ? g_Zpart[tid] : 0.f;
    #pragma unroll
    for (int o = 16; o; o >>= 1) z += __shfl_xor_sync(0xffffffffu, z, o);
    if (lane == 0) sz[row] = z;
    __syncthreads();

    if (tid < DIM) {
        float tot = 0.f;
        #pragma unroll
        for (int r = 0; r < 32; r++) tot += su[r][tid];
        float zz = 0.f;
        #pragma unroll
        for (int w = 0; w < 32; w++) zz += sz[w];   // threads 0..455 covered: 456 <= 1024 -> warps 0..14 contributed; rest zero
        out[tid] = tot / zz;
    }
}

static const int SMEM_BYTES = (TILE * DIM + 136) * (int)sizeof(float);

extern "C" void kernel_launch(void* const* d_in, const int* in_sizes, int n_in,
                              void* d_out, int out_size) {
    // Bind inputs by UNIQUE element count (robust to metadata ordering):
    // x=1024, prev=524288 (unused: gate==1), mem=67108864, W=141312, b=138
    const float *x = 0, *mem = 0, *W = 0, *b = 0;
    for (int i = 0; i < n_in; i++) {
        switch (in_sizes[i]) {
            case DIN:            x   = (const float*)d_in[i]; break;
            case N_SLOTS * DIM:  mem = (const float*)d_in[i]; break;
            case DIN * NF:       W   = (const float*)d_in[i]; break;
            case NF:             b   = (const float*)d_in[i]; break;
            default: break;      // previous_weighting (N_SLOTS): unused
        }
    }
    float* out = (float*)d_out;

    cudaFuncSetAttribute(k_main, cudaFuncAttributeMaxDynamicSharedMemorySize, SMEM_BYTES);

    k_factors<<<(NF + 31) / 32, TPB>>>(x, W, b);
    k_prep<<<1, 128>>>();
    k_main<<<MAIN_BLOCKS, TPB, SMEM_BYTES>>>(mem);
    k_fin<<<1, 1024>>>(out);
}

// round 5
// speedup vs baseline: 1.7330x; 1.6766x over previous
#include <cuda_runtime.h>

#define N_SLOTS 524288
#define DIM     128
#define NF      138        // DIM_MEM + 1 + 1 + 7 + 1
#define DIN     1024
#define TILE    128
#define HALO    3
#define TPB     256
#define NWARPS  8
#define NTILES  (N_SLOTS / TILE)    // 4096
#define MAIN_BLOCKS 304             // 2 per SM on 152 SMs
#define KBLK    8
#define FBLK    5

// scratch (allocation-free: __device__ globals)
__device__ __align__(16) float g_fpart[KBLK][160];
__device__ float g_UpartT[DIM][MAIN_BLOCKS];
__device__ float g_Zpart[MAIN_BLOCKS];

// ---------------- K1: partial factors  fpart[kb][f] = sum_{k in chunk kb} x[k]*W[k,f] ----------------
__global__ void k_factors(const float* __restrict__ x,
                          const float* __restrict__ W) {
    const int fb   = blockIdx.x % FBLK;
    const int kb   = blockIdx.x / FBLK;
    const int tid  = threadIdx.x;
    const int warp = tid >> 5;
    const int lane = tid & 31;
    const int f    = fb * 32 + lane;

    float acc = 0.f;
    if (f < NF) {
        const int kbase = kb * 128 + warp * 16;
        #pragma unroll
        for (int i = 0; i < 16; i++)
            acc += __ldg(&x[kbase + i]) * __ldg(&W[(kbase + i) * NF + f]);
    }
    __shared__ float su[NWARPS][32];
    su[warp][lane] = acc;
    __syncthreads();
    if (warp == 0) {
        float s = acc;
        #pragma unroll
        for (int w = 1; w < NWARPS; w++) s += su[w][lane];
        g_fpart[kb][fb * 32 + lane] = s;
    }
}

// ---------------- K2: fused single pass over memory (per-block redundant prep) ----------------
__global__ void __launch_bounds__(TPB, 2) k_main(const float* __restrict__ mem,
                                                 const float* __restrict__ bvec) {
    __shared__ __align__(16) float sF[144];   // factors
    __shared__ float sP[12];                  // 0:ks 1:stab 2:ikn 3:sharp 4..10:shift
    __shared__ float sE[136];
    __shared__ float sRed[NWARPS * DIM];      // 4 KB final reduction
    __shared__ float sZw[NWARPS];

    const int tid  = threadIdx.x;
    const int warp = tid >> 5;
    const int lane = tid & 31;

    // ---- per-block prep (reads 8x160 partials from L2) ----
    if (tid < 144) {
        float s = 0.f;
        if (tid < NF) {
            #pragma unroll
            for (int p = 0; p < KBLK; p++) s += g_fpart[p][tid];
            s += bvec[tid];
        }
        sF[tid] = s;
    }
    __syncthreads();
    if (warp < 4) {
        const float v = sF[warp * 32 + lane];
        float sq = v * v;
        #pragma unroll
        for (int o = 16; o; o >>= 1) sq += __shfl_xor_sync(0xffffffffu, sq, o);
        if (lane == 0) sZw[warp] = sq;
    }
    __syncthreads();
    if (tid == 0) {
        const float tot = sZw[0] + sZw[1] + sZw[2] + sZw[3];
        const float ks  = sF[DIM];
        sP[0] = ks;
        sP[1] = fabsf(ks);
        sP[2] = 1.f / fmaxf(sqrtf(tot), 1e-8f);
        sP[3] = fmaxf(sF[NF - 1], 0.f) + 1.f;
        float mx = -1e30f;
        #pragma unroll
        for (int j = 0; j < 7; j++) mx = fmaxf(mx, sF[DIM + 2 + j]);
        float ssum = 0.f, ev[7];
        #pragma unroll
        for (int j = 0; j < 7; j++) { ev[j] = expf(sF[DIM + 2 + j] - mx); ssum += ev[j]; }
        #pragma unroll
        for (int j = 0; j < 7; j++) sP[4 + j] = ev[j] / ssum;
    }
    __syncthreads();
    // gate = softmax(single element) == 1.0 exactly -> previous_weighting unused.

    const float4 kv = ((const float4*)sF)[lane];
    const float ks = sP[0], stab = sP[1], ikn = sP[2], sharp = sP[3];
    float sh[7];
    #pragma unroll
    for (int j = 0; j < 7; j++) sh[j] = sP[4 + j];

    // halo row (sE index) owned by this warp, or -1
    const int halo_l = (warp < 3) ? warp : ((warp >= 5) ? (126 + warp) : -1);
    const int r0 = warp * 16;            // first owned tile row

    float4 acc = make_float4(0.f, 0.f, 0.f, 0.f);
    float zacc = 0.f;

    for (int t = blockIdx.x; t < NTILES; t += MAIN_BLOCKS) {
        const int gStart = t * TILE;

        // ---- halo e (wraps only at array ends) ----
        if (halo_l >= 0) {
            int g = gStart + halo_l - HALO;
            g += (g < 0) ? N_SLOTS : 0;
            g -= (g >= N_SLOTS) ? N_SLOTS : 0;
            const float4 mh = ((const float4*)(mem + (size_t)g * DIM))[lane];
            float d = mh.x*kv.x + mh.y*kv.y + mh.z*kv.z + mh.w*kv.w;
            float q = mh.x*mh.x + mh.y*mh.y + mh.z*mh.z + mh.w*mh.w;
            #pragma unroll
            for (int o = 16; o; o >>= 1) {
                d += __shfl_xor_sync(0xffffffffu, d, o);
                q += __shfl_xor_sync(0xffffffffu, q, o);
            }
            if (lane == 0) {
                const float c = d * ikn * rsqrtf(fmaxf(q, 1e-16f));
                sE[halo_l] = __expf(ks * c - stab);
            }
        }

        // ---- owned rows: burst-load 16 rows (8 KB in flight per warp) ----
        const float* rowp = mem + (size_t)(gStart + r0) * DIM;
        float4 m[16];
        #pragma unroll
        for (int i = 0; i < 16; i++)
            m[i] = ((const float4*)(rowp + i * DIM))[lane];

        #pragma unroll
        for (int i0 = 0; i0 < 16; i0 += 4) {
            float d[4], q[4];
            #pragma unroll
            for (int u = 0; u < 4; u++) {
                const float4 mm = m[i0 + u];
                d[u] = mm.x*kv.x + mm.y*kv.y + mm.z*kv.z + mm.w*kv.w;
                q[u] = mm.x*mm.x + mm.y*mm.y + mm.z*mm.z + mm.w*mm.w;
            }
            #pragma unroll
            for (int o = 16; o; o >>= 1) {
                #pragma unroll
                for (int u = 0; u < 4; u++) {
                    d[u] += __shfl_xor_sync(0xffffffffu, d[u], o);
                    q[u] += __shfl_xor_sync(0xffffffffu, q[u], o);
                }
            }
            if (lane == 0) {
                #pragma unroll
                for (int u = 0; u < 4; u++) {
                    const float c = d[u] * ikn * rsqrtf(fmaxf(q[u], 1e-16f));
                    sE[HALO + r0 + i0 + u] = __expf(ks * c - stab);
                }
            }
        }
        __syncthreads();   // all e of this tile visible

        // ---- pw for owned rows; lanes 0..15 ----
        float pw = 0.f;
        if (lane < 16) {
            float tc = 0.f;
            #pragma unroll
            for (int j = 0; j < 7; j++) tc += sh[j] * sE[r0 + lane + j];
            pw = __powf(tc, sharp);       // tc>0 always
            zacc += pw;
        }
        __syncthreads();   // sE fully consumed; next tile may overwrite

        // ---- accumulate from registers ----
        #pragma unroll
        for (int r = 0; r < 16; r++) {
            const float pwb = __shfl_sync(0xffffffffu, pw, r);
            acc.x += pwb * m[r].x; acc.y += pwb * m[r].y;
            acc.z += pwb * m[r].z; acc.w += pwb * m[r].w;
        }
    }

    // ---- deterministic in-block reduction, transposed global store ----
    __syncthreads();
    ((float4*)(sRed + warp * DIM))[lane] = acc;
    #pragma unroll
    for (int o = 16; o; o >>= 1) zacc += __shfl_xor_sync(0xffffffffu, zacc, o);
    if (lane == 0) sZw[warp] = zacc;
    __syncthreads();
    if (tid < DIM) {
        float u = 0.f;
        #pragma unroll
        for (int w = 0; w < NWARPS; w++) u += sRed[w * DIM + tid];
        g_UpartT[tid][blockIdx.x] = u;
    }
    if (tid == 0) {
        float z = 0.f;
        #pragma unroll
        for (int w = 0; w < NWARPS; w++) z += sZw[w];
        g_Zpart[blockIdx.x] = z;
    }
}

// ---------------- K3: final reduction + normalize (coalesced rows) ----------------
__global__ void k_fin(float* __restrict__ out) {
    const int tid  = threadIdx.x;   // 1024
    const int warp = tid >> 5;
    const int lane = tid & 31;

    float z = 0.f;
    for (int i = lane; i < MAIN_BLOCKS; i += 32) z += g_Zpart[i];
    #pragma unroll
    for (int o = 16; o; o >>= 1) z += __shfl_xor_sync(0xffffffffu, z, o);

    for (int d = warp; d < DIM; d += 32) {
        float u = 0.f;
        for (int i = lane; i < MAIN_BLOCKS; i += 32) u += g_UpartT[d][i];
        #pragma unroll
        for (int o = 16; o; o >>= 1) u += __shfl_xor_sync(0xffffffffu, u, o);
        if (lane == 0) out[d] = u / z;
    }
}

extern "C" void kernel_launch(void* const* d_in, const int* in_sizes, int n_in,
                              void* d_out, int out_size) {
    // Bind inputs by UNIQUE element count (robust to metadata ordering):
    // x=1024, prev=524288 (unused: gate==1), mem=67108864, W=141312, b=138
    const float *x = 0, *mem = 0, *W = 0, *b = 0;
    for (int i = 0; i < n_in; i++) {
        switch (in_sizes[i]) {
            case DIN:            x   = (const float*)d_in[i]; break;
            case N_SLOTS * DIM:  mem = (const float*)d_in[i]; break;
            case DIN * NF:       W   = (const float*)d_in[i]; break;
            case NF:             b   = (const float*)d_in[i]; break;
            default: break;      // previous_weighting (N_SLOTS): unused
        }
    }
    float* out = (float*)d_out;

    k_factors<<<FBLK * KBLK, TPB>>>(x, W);
    k_main<<<MAIN_BLOCKS, TPB>>>(mem, b);
    k_fin<<<1, 1024>>>(out);
}